// round 16
// baseline (speedup 1.0000x reference)
#include <cuda_runtime.h>
#include <cuda_fp16.h>
#include <math.h>
#include <stdint.h>

#define Bv 2
#define Tv 2048
#define Dv 1024
#define Hv 16
#define HDv 64
#define Mv (Bv*Tv)
#define NELEM (Mv*Dv)
#define NCk 32      // chunks per sequence
#define CLk 64      // chunk length

// ---------------- helpers ----------------
__device__ __forceinline__ uint32_t smem_u32(const void* p) {
    uint32_t a;
    asm("{ .reg .u64 t; cvta.to.shared.u64 t, %1; cvt.u32.u64 %0, t; }" : "=r"(a) : "l"(p));
    return a;
}
#define SWZ(off) ((off) ^ (((off) >> 3) & 0x70))

__device__ __forceinline__ void ldsm_x4(uint32_t* r, uint32_t addr) {
    asm volatile("ldmatrix.sync.aligned.m8n8.x4.shared.b16 {%0,%1,%2,%3}, [%4];"
        : "=r"(r[0]), "=r"(r[1]), "=r"(r[2]), "=r"(r[3]) : "r"(addr));
}
__device__ __forceinline__ void hmma(float* c, const uint32_t* a, const uint32_t* b) {
    asm volatile(
        "mma.sync.aligned.m16n8k16.row.col.f32.f16.f16.f32 "
        "{%0,%1,%2,%3}, {%4,%5,%6,%7}, {%8,%9}, {%0,%1,%2,%3};"
        : "+f"(c[0]), "+f"(c[1]), "+f"(c[2]), "+f"(c[3])
        : "r"(a[0]), "r"(a[1]), "r"(a[2]), "r"(a[3]), "r"(b[0]), "r"(b[1]));
}
__device__ __forceinline__ void cp16(uint32_t dst, const void* src, int srcsize) {
    asm volatile("cp.async.cg.shared.global [%0], [%1], 16, %2;"
        :: "r"(dst), "l"(src), "r"(srcsize) : "memory");
}
#define CP_COMMIT() asm volatile("cp.async.commit_group;" ::: "memory")
#define CP_WAIT(N)  asm volatile("cp.async.wait_group %0;" :: "n"(N) : "memory")

__device__ __forceinline__ uint32_t h2u(__half a, __half b) {
    __half2 p = __halves2half2(a, b);
    return *reinterpret_cast<uint32_t*>(&p);
}

// ---------------- scratch globals ----------------
__device__ __align__(16) float g_mixt[Mv*160];
__device__ __align__(16) float g_gate[NELEM];
__device__ __align__(16) float g_e[NELEM];          // exp(glog), fp32

// chunked-scan scratch
__device__ __align__(16) float g_oloc[NELEM];
__device__ __align__(16) float g_qd[NELEM];
__device__ __align__(16) float g_slocal[32 * NCk * 4096];
__device__ __align__(16) float g_sin[32 * NCk * 4096];
__device__ __align__(16) float g_dprod[32 * NCk * 64];

// fp16 activations
__device__ __align__(16) __half g_xx_h[NELEM];
__device__ __align__(16) __half g_xr_h[NELEM];
__device__ __align__(16) __half g_xk_h[NELEM];
__device__ __align__(16) __half g_xv_h[NELEM];
__device__ __align__(16) __half g_xw_h[NELEM];
__device__ __align__(16) __half g_xg_h[NELEM];
__device__ __align__(16) __half g_dt_h[Mv*64];
__device__ __align__(16) __half g_o_h[NELEM];
__device__ __align__(16) __half g_q_h[NELEM];
__device__ __align__(16) __half g_k_h[NELEM];
__device__ __align__(16) __half g_v_h[NELEM];

// weight pool (transposed, fp16): [N][K]
#define OFF_WQ  0
#define OFF_WK  1048576
#define OFF_WV  2097152
#define OFF_WG  3145728
#define OFF_WO  4194304
#define OFF_DW1 5242880
#define OFF_DW2 (5242880 + 65536)
#define OFF_W1  (5242880 + 131072)
#define WPOOL_SZ (5242880 + 131072 + 163840)
__device__ __align__(16) __half g_w16[WPOOL_SZ];

// ---------------- elementwise ----------------
// xx = x + (xprev - x)*maa_x -> fp16  (xprev = 0 at t=0)
__global__ __launch_bounds__(256) void shift_kernel(const float* __restrict__ x,
                                                    const float* __restrict__ maa_x) {
    int i = blockIdx.x * 256 + threadIdx.x;
    float xv = x[i];
    int d  = i & (Dv - 1);
    int tt = (i >> 10) & (Tv - 1);
    float xp = (tt > 0) ? x[i - Dv] : 0.f;
    g_xx_h[i] = __float2half_rn(fmaf(xp - xv, maa_x[d], xv));
}

// all weights: W[K][N] -> fp16 [N][K] in pool
__global__ __launch_bounds__(1024)
void wprep_all(const float* __restrict__ Wq, const float* __restrict__ Wk,
               const float* __restrict__ Wv, const float* __restrict__ Wg,
               const float* __restrict__ Wo, const float* __restrict__ dw1,
               const float* __restrict__ dw2, const float* __restrict__ w1,
               __half* __restrict__ pool)
{
    __shared__ float tile[32][33];
    const float* W; int K, N; int off;
    switch (blockIdx.z) {
        case 0: W = Wq;  K = 1024; N = 1024; off = OFF_WQ;  break;
        case 1: W = Wk;  K = 1024; N = 1024; off = OFF_WK;  break;
        case 2: W = Wv;  K = 1024; N = 1024; off = OFF_WV;  break;
        case 3: W = Wg;  K = 1024; N = 1024; off = OFF_WG;  break;
        case 4: W = Wo;  K = 1024; N = 1024; off = OFF_WO;  break;
        case 5: W = dw1; K = 1024; N = 64;   off = OFF_DW1; break;
        case 6: W = dw2; K = 64;   N = 1024; off = OFF_DW2; break;
        default:W = w1;  K = 1024; N = 160;  off = OFF_W1;  break;
    }
    int bx = blockIdx.x, by = blockIdx.y;
    if (bx * 32 >= N || by * 32 >= K) return;
    int tx = threadIdx.x, ty = threadIdx.y;
    tile[ty][tx] = W[(size_t)(by * 32 + ty) * N + bx * 32 + tx];
    __syncthreads();
    int n2 = bx * 32 + ty, k2 = by * 32 + tx;
    if (n2 < N)
        pool[off + (size_t)n2 * K + k2] = __float2half_rn(tile[tx][ty]);
}

// ---------------- GEMM core: single-pass fp16, cp.async 2-stage ----------------
// epi: 0 = acc*scale ; 1 = tanh ; 2 = exp(-exp(bias[n]+acc)) ; 3 = silu(acc+bias[n])
__device__ __forceinline__ void gemm_core(
    const __half* __restrict__ Ah, const __half* __restrict__ Bm,
    const float* __restrict__ bias,
    float* __restrict__ Cf, __half* __restrict__ Chi,
    int ldC, int Ntot, int K, float scale, int epi, int osplit,
    int m0, int n0, uint32_t sb0)
{
    constexpr uint32_t STAGE = 32768;
    constexpr uint32_t A_OF = 0, B_OF = 16384;
    const int t = threadIdx.x, wid = t >> 5, lane = t & 31;
    const int wm = (wid & 1) * 64, wn = (wid >> 1) * 32;
    const int ldrow = t >> 3;
    const int kseg = (t & 7) * 8;
    const uint32_t dsw = SWZ((uint32_t)(ldrow * 128 + (t & 7) * 16));
    const int nch = K >> 6;

    auto issue = [&](int c) {
        const int k0 = c << 6;
        const uint32_t sb = sb0 + (uint32_t)(c & 1) * STAGE;
#pragma unroll
        for (int it = 0; it < 4; it++) {
            int row = it * 32 + ldrow;
            size_t ga = (size_t)(m0 + row) * K + k0 + kseg;
            cp16(sb + A_OF + it * 4096 + dsw, Ah + ga, 16);
            int nr = n0 + row;
            int ss = (nr < Ntot) ? 16 : 0;
            size_t gb = (size_t)(nr < Ntot ? nr : 0) * K + k0 + kseg;
            cp16(sb + B_OF + it * 4096 + dsw, Bm + gb, ss);
        }
        CP_COMMIT();
    };

    issue(0);

    float acc[4][4][4];
#pragma unroll
    for (int a = 0; a < 4; a++)
#pragma unroll
        for (int b = 0; b < 4; b++)
#pragma unroll
            for (int cc = 0; cc < 4; cc++) acc[a][b][cc] = 0.f;

    const int rowA_l = (lane & 7) + ((lane >> 3) & 1) * 8;
    const int koffA  = ((lane >> 4) & 1) * 16;
    const uint32_t xorA = (uint32_t)((rowA_l & 7) << 4);
    const int rowB_l = (lane & 7) + ((lane >> 4) & 1) * 8;
    const int koffB  = ((lane >> 3) & 1) * 16;
    const uint32_t xorB = (uint32_t)((rowB_l & 7) << 4);

    for (int c = 0; c < nch; c++) {
        if (c + 1 < nch) { issue(c + 1); CP_WAIT(1); }
        else             { CP_WAIT(0); }
        __syncthreads();
        const uint32_t sb = sb0 + (uint32_t)(c & 1) * STAGE;
#pragma unroll
        for (int ks = 0; ks < 4; ks++) {
            const uint32_t kbA = (uint32_t)(ks * 32 + koffA) ^ xorA;
            const uint32_t kbB = (uint32_t)(ks * 32 + koffB) ^ xorB;
            uint32_t bf[4][2];
#pragma unroll
            for (int pt = 0; pt < 2; pt++) {
                uint32_t r[4];
                uint32_t baddr = (uint32_t)((wn + pt * 16 + rowB_l) * 128) + kbB;
                ldsm_x4(r, sb + B_OF + baddr);
                bf[2*pt][0] = r[0]; bf[2*pt][1] = r[1];
                bf[2*pt+1][0] = r[2]; bf[2*pt+1][1] = r[3];
            }
#pragma unroll
            for (int mi = 0; mi < 4; mi++) {
                uint32_t ah[4];
                uint32_t aaddr = (uint32_t)((wm + mi * 16 + rowA_l) * 128) + kbA;
                ldsm_x4(ah, sb + A_OF + aaddr);
#pragma unroll
                for (int ni = 0; ni < 4; ni++)
                    hmma(acc[mi][ni], ah, bf[ni]);
            }
        }
        __syncthreads();
    }

    // epilogue
    const int rfrag = lane >> 2;
    const int cfrag = (lane & 3) * 2;
#pragma unroll
    for (int mi = 0; mi < 4; mi++) {
#pragma unroll
        for (int ni = 0; ni < 4; ni++) {
            int n = n0 + wn + ni * 8 + cfrag;
            if (n >= Ntot) continue;
            int r0 = m0 + wm + mi * 16 + rfrag;
            float b0 = 0.f, b1 = 0.f;
            if (epi == 2 || epi == 3) { b0 = bias[n]; b1 = bias[n + 1]; }
#pragma unroll
            for (int hh = 0; hh < 2; hh++) {
                float vx = acc[mi][ni][hh * 2], vy = acc[mi][ni][hh * 2 + 1];
                float ox, oy;
                if (epi == 0)      { ox = vx * scale; oy = vy * scale; }
                else if (epi == 1) { ox = tanhf(vx); oy = tanhf(vy); }
                else if (epi == 2) { ox = expf(-expf(b0 + vx)); oy = expf(-expf(b1 + vy)); }
                else {
                    float z0 = vx + b0, z1 = vy + b1;
                    ox = z0 / (1.f + expf(-z0)); oy = z1 / (1.f + expf(-z1));
                }
                size_t idx = (size_t)(r0 + hh * 8) * ldC + n;
                if (osplit) {
                    *(uint32_t*)(Chi + idx) = h2u(__float2half_rn(ox), __float2half_rn(oy));
                } else {
                    *(float2*)(Cf + idx) = make_float2(ox, oy);
                }
            }
        }
    }
}

// ---- GEMM wrappers ----
__global__ __launch_bounds__(256, 2)
void mixpre_kernel(const __half* __restrict__ wpool)
{
    extern __shared__ char smraw[];
    gemm_core(g_xx_h, wpool + OFF_W1, nullptr, g_mixt, nullptr,
              160, 160, 1024, 1.f, 1, 0, blockIdx.y * 128, blockIdx.x * 128, smem_u32(smraw));
}

__global__ __launch_bounds__(256, 2)
void proj_kernel(const __half* __restrict__ wpool, const float* __restrict__ bg)
{
    extern __shared__ char smraw[];
    int z = blockIdx.z;
    if (z == 4 && blockIdx.x > 0) return;
    const __half *Ah, *Bm;
    const float* bias = nullptr;
    float* Cf = nullptr; __half* Chi = nullptr;
    int Ntot = 1024, ldC = 1024, epi = 0, osplit = 0;
    float scale = 1.f;
    switch (z) {
        case 0: Ah = g_xr_h; Bm = wpool + OFF_WQ; Chi = g_q_h; osplit = 1; scale = 0.125f; break;
        case 1: Ah = g_xk_h; Bm = wpool + OFF_WK; Chi = g_k_h; osplit = 1; break;
        case 2: Ah = g_xv_h; Bm = wpool + OFF_WV; Chi = g_v_h; osplit = 1; break;
        case 3: Ah = g_xg_h; Bm = wpool + OFF_WG; bias = bg; Cf = g_gate; epi = 3; break;
        default: Ah = g_xw_h; Bm = wpool + OFF_DW1;
                 Chi = g_dt_h; Ntot = 64; ldC = 64; epi = 1; osplit = 1; break;
    }
    gemm_core(Ah, Bm, bias, Cf, Chi, ldC, Ntot, 1024, scale, epi, osplit,
              blockIdx.y * 128, blockIdx.x * 128, smem_u32(smraw));
}

// e = exp(glog) = exp(-exp(tdecay + dt@dw2)), stored fp32
__global__ __launch_bounds__(256, 2)
void glog_kernel(const __half* __restrict__ wpool, const float* __restrict__ tdecay)
{
    extern __shared__ char smraw[];
    gemm_core(g_dt_h, wpool + OFF_DW2, tdecay, g_e, nullptr,
              1024, 1024, 64, 1.f, 2, 0, blockIdx.y * 128, blockIdx.x * 128, smem_u32(smraw));
}

__global__ __launch_bounds__(256, 2)
void wo_kernel(const __half* __restrict__ wpool, float* __restrict__ out)
{
    extern __shared__ char smraw[];
    gemm_core(g_o_h, wpool + OFF_WO, nullptr, out, nullptr,
              1024, 1024, 1024, 1.f, 0, 0, blockIdx.y * 128, blockIdx.x * 128, smem_u32(smraw));
}

// ---------------- 5-stream mix (dx fused, fp16 out) ----------------
#define MF_SMEM 55296
__global__ __launch_bounds__(256)
void mix5_kernel(const float* __restrict__ x, const float* __restrict__ w2,
                 const float* __restrict__ mr, const float* __restrict__ mk,
                 const float* __restrict__ mv_, const float* __restrict__ mw,
                 const float* __restrict__ mg)
{
    extern __shared__ float sm[];
    float* smixt = sm;            // [32][160]
    float* sw2   = sm + 5120;     // [32][128]
    float* sxt   = sm + 9216;     // [33][128]

    const int t = threadIdx.x;
    const int c0 = blockIdx.x * 128;
    const int m0 = blockIdx.y * 32;
    const int tx = t & 31, ty = t >> 5;

    for (int i = t; i < 1280; i += 256) {
        int row = i / 40, c4 = i % 40;
        *(float4*)&smixt[row * 160 + c4 * 4] =
            *(const float4*)(g_mixt + (size_t)(m0 + row) * 160 + c4 * 4);
    }
    // x rows m0-1 .. m0+31; sequence-start boundary row = zeros
    for (int i = t; i < 33 * 32; i += 256) {
        int row = i >> 5, c4 = i & 31;
        float4 val;
        if (row == 0 && (m0 & (Tv - 1)) == 0) {
            val = make_float4(0.f, 0.f, 0.f, 0.f);
        } else {
            int grow = m0 + row - 1;
            val = *(const float4*)(x + (size_t)grow * 1024 + c0 + c4 * 4);
        }
        *(float4*)&sxt[row * 128 + c4 * 4] = val;
    }

    const float* maas[5] = {mr, mk, mv_, mw, mg};
    __half* oh[5] = {g_xr_h, g_xk_h, g_xv_h, g_xw_h, g_xg_h};

#pragma unroll 1
    for (int s = 0; s < 5; s++) {
        __syncthreads();
        for (int i = t; i < 1024; i += 256) {
            int row = i >> 5, c4 = i & 31;
            *(float4*)&sw2[row * 128 + c4 * 4] =
                *(const float4*)(w2 + ((size_t)s * 32 + row) * 1024 + c0 + c4 * 4);
        }
        __syncthreads();

        float acc[4][4];
#pragma unroll
        for (int i = 0; i < 4; i++)
#pragma unroll
            for (int j = 0; j < 4; j++) acc[i][j] = 0.f;
#pragma unroll
        for (int k4 = 0; k4 < 8; k4++) {
            float4 a4[4];
#pragma unroll
            for (int i = 0; i < 4; i++)
                a4[i] = *(const float4*)&smixt[(ty * 4 + i) * 160 + s * 32 + k4 * 4];
#pragma unroll
            for (int kk = 0; kk < 4; kk++) {
                float4 w4 = *(const float4*)&sw2[(k4 * 4 + kk) * 128 + tx * 4];
#pragma unroll
                for (int i = 0; i < 4; i++) {
                    float a = (kk == 0) ? a4[i].x : (kk == 1) ? a4[i].y
                             : (kk == 2) ? a4[i].z : a4[i].w;
                    acc[i][0] = fmaf(a, w4.x, acc[i][0]);
                    acc[i][1] = fmaf(a, w4.y, acc[i][1]);
                    acc[i][2] = fmaf(a, w4.z, acc[i][2]);
                    acc[i][3] = fmaf(a, w4.w, acc[i][3]);
                }
            }
        }

        float4 ma4 = *(const float4*)(maas[s] + c0 + tx * 4);
        __half* ohp = oh[s];
#pragma unroll
        for (int i = 0; i < 4; i++) {
            int row = ty * 4 + i;
            float4 xv4 = *(const float4*)&sxt[(row + 1) * 128 + tx * 4];
            float4 xp4 = *(const float4*)&sxt[row * 128 + tx * 4];
            float o0 = fmaf(xp4.x - xv4.x, ma4.x + acc[i][0], xv4.x);
            float o1 = fmaf(xp4.y - xv4.y, ma4.y + acc[i][1], xv4.y);
            float o2 = fmaf(xp4.z - xv4.z, ma4.z + acc[i][2], xv4.z);
            float o3 = fmaf(xp4.w - xv4.w, ma4.w + acc[i][3], xv4.w);
            size_t gi = (size_t)(m0 + row) * 1024 + c0 + tx * 4;
            *(uint2*)(ohp + gi) = make_uint2(
                h2u(__float2half_rn(o0), __float2half_rn(o1)),
                h2u(__float2half_rn(o2), __float2half_rn(o3)));
        }
    }
}

// ---------------- chunked scan ----------------
// roles: kg0 -> q (fp16), kg1 -> k*(1-e) (fp16 k, fp32 e), kg2 -> e (fp32), kg3 -> v (fp16)
#define S1_LOAD(T_, R) do { \
    size_t off = cbase + (size_t)(T_) * Dv; \
    if (kg == 0)      R = __half2float(g_q_h[off + lidx]); \
    else if (kg == 1) { size_t i = off + lidx; \
                        R = __half2float(g_k_h[i]) * (1.f - g_e[i]); } \
    else if (kg == 2) R = g_e[off + lidx]; \
    else              R = __half2float(g_v_h[off + lidx]); \
} while (0)

__global__ __launch_bounds__(256)
void scan1_kernel() {
    const int bh = blockIdx.y;
    const int b = bh >> 4, h = bh & 15;
    const int c = blockIdx.x;
    const int tid = threadIdx.x;
    const int vcol = tid & 63;
    const int kg = tid >> 6;
    const int k0 = kg * 16;
    const int lidx = tid & 63;

    __shared__ __align__(16) float sq[64];
    __shared__ __align__(16) float sk[64];
    __shared__ __align__(16) float se[64];
    __shared__ __align__(16) float sv[64];
    __shared__ float spart[4][64];

    float S[16];
#pragma unroll
    for (int j = 0; j < 16; j++) S[j] = 0.f;
    float cum = 1.f;

    const size_t base0 = (size_t)b * Tv * Dv + h * HDv;
    const size_t cbase = base0 + (size_t)(c * CLk) * Dv;

    float r0, r1;
    S1_LOAD(0, r0);
    S1_LOAD(1, r1);

    for (int t = 0; t < CLk; t += 2) {
        if (kg == 0)      sq[lidx] = r0;
        else if (kg == 1) sk[lidx] = r0;
        else if (kg == 2) { se[lidx] = r0; cum *= r0; }
        else              sv[lidx] = r0;
        __syncthreads();
        if (t + 2 < CLk) S1_LOAD(t + 2, r0);
        if (kg == 2) g_qd[cbase + (size_t)t * Dv + lidx] = cum * sq[lidx];
        {
            const float vv = sv[vcol];
            float p0 = 0.f, p1 = 0.f;
#pragma unroll
            for (int jj = 0; jj < 4; jj++) {
                float4 e4 = *(const float4*)&se[k0 + jj * 4];
                float4 k4 = *(const float4*)&sk[k0 + jj * 4];
                float4 q4 = *(const float4*)&sq[k0 + jj * 4];
                S[jj*4+0] = fmaf(S[jj*4+0], e4.x, k4.x * vv); p0 = fmaf(q4.x, S[jj*4+0], p0);
                S[jj*4+1] = fmaf(S[jj*4+1], e4.y, k4.y * vv); p1 = fmaf(q4.y, S[jj*4+1], p1);
                S[jj*4+2] = fmaf(S[jj*4+2], e4.z, k4.z * vv); p0 = fmaf(q4.z, S[jj*4+2], p0);
                S[jj*4+3] = fmaf(S[jj*4+3], e4.w, k4.w * vv); p1 = fmaf(q4.w, S[jj*4+3], p1);
            }
            spart[kg][vcol] = p0 + p1;
        }
        __syncthreads();
        if (kg == 0)
            g_oloc[cbase + (size_t)t * Dv + vcol] =
                spart[0][vcol] + spart[1][vcol] + spart[2][vcol] + spart[3][vcol];

        if (kg == 0)      sq[lidx] = r1;
        else if (kg == 1) sk[lidx] = r1;
        else if (kg == 2) { se[lidx] = r1; cum *= r1; }
        else              sv[lidx] = r1;
        __syncthreads();
        if (t + 3 < CLk) S1_LOAD(t + 3, r1);
        if (kg == 2) g_qd[cbase + (size_t)(t + 1) * Dv + lidx] = cum * sq[lidx];
        {
            const float vv = sv[vcol];
            float p0 = 0.f, p1 = 0.f;
#pragma unroll
            for (int jj = 0; jj < 4; jj++) {
                float4 e4 = *(const float4*)&se[k0 + jj * 4];
                float4 k4 = *(const float4*)&sk[k0 + jj * 4];
                float4 q4 = *(const float4*)&sq[k0 + jj * 4];
                S[jj*4+0] = fmaf(S[jj*4+0], e4.x, k4.x * vv); p0 = fmaf(q4.x, S[jj*4+0], p0);
                S[jj*4+1] = fmaf(S[jj*4+1], e4.y, k4.y * vv); p1 = fmaf(q4.y, S[jj*4+1], p1);
                S[jj*4+2] = fmaf(S[jj*4+2], e4.z, k4.z * vv); p0 = fmaf(q4.z, S[jj*4+2], p0);
                S[jj*4+3] = fmaf(S[jj*4+3], e4.w, k4.w * vv); p1 = fmaf(q4.w, S[jj*4+3], p1);
            }
            spart[kg][vcol] = p0 + p1;
        }
        __syncthreads();
        if (kg == 0)
            g_oloc[cbase + (size_t)(t + 1) * Dv + vcol] =
                spart[0][vcol] + spart[1][vcol] + spart[2][vcol] + spart[3][vcol];
    }

    size_t sbase = (size_t)(bh * NCk + c) * 4096;
#pragma unroll
    for (int j = 0; j < 16; j++)
        g_slocal[sbase + (size_t)(k0 + j) * 64 + vcol] = S[j];
    if (kg == 2)
        g_dprod[(bh * NCk + c) * 64 + lidx] = cum;
}

// scan2: sequential diagonal combine across chunks -> S_in per chunk
__global__ __launch_bounds__(256)
void scan2_kernel() {
    const int bh = blockIdx.x;
    const int tid = threadIdx.x;
    float s[16];
#pragma unroll
    for (int i = 0; i < 16; i++) s[i] = 0.f;
    for (int c = 0; c < NCk; c++) {
        size_t base = (size_t)(bh * NCk + c) * 4096;
#pragma unroll
        for (int i = 0; i < 16; i++) {
            int cell = tid + i * 256;
            g_sin[base + cell] = s[i];
            float dp = g_dprod[(bh * NCk + c) * 64 + (cell >> 6)];
            s[i] = fmaf(dp, s[i], g_slocal[base + cell]);
        }
    }
}

// scan3: o_t = (o_loc_t + Qd_t . S_in) * gate -> fp16 output
#define S3_SMEM 32768
__global__ __launch_bounds__(256)
void scan3_kernel() {
    extern __shared__ float s3[];
    float* ssin = s3;              // 4096
    float* sqd  = s3 + 4096;       // 4096

    const int bh = blockIdx.y;
    const int b = bh >> 4, h = bh & 15;
    const int c = blockIdx.x;
    const int tid = threadIdx.x;
    const size_t base0 = (size_t)b * Tv * Dv + h * HDv;
    const size_t cbase = base0 + (size_t)(c * CLk) * Dv;

    {
        const float* sinp = g_sin + (size_t)(bh * NCk + c) * 4096;
        for (int i = tid; i < 1024; i += 256)
            *(float4*)&ssin[i * 4] = *(const float4*)(sinp + i * 4);
        for (int i = tid; i < CLk * 16; i += 256) {
            int row = i >> 4, cg = i & 15;
            *(float4*)&sqd[row * 64 + cg * 4] =
                *(const float4*)(g_qd + cbase + (size_t)row * Dv + cg * 4);
        }
    }
    __syncthreads();

    const int tg = tid >> 6;
    const int v = tid & 63;
    constexpr int TPT = CLk / 4;

    float acc[TPT];
#pragma unroll
    for (int i = 0; i < TPT; i++)
        acc[i] = g_oloc[cbase + (size_t)(tg + i * 4) * Dv + v];

#pragma unroll 1
    for (int kb = 0; kb < 64; kb += 16) {
        float sinr[16];
#pragma unroll
        for (int j = 0; j < 16; j++) sinr[j] = ssin[(kb + j) * 64 + v];
#pragma unroll
        for (int i = 0; i < TPT; i++) {
            const int ti = tg + i * 4;
            const float* qrow = &sqd[ti * 64 + kb];
#pragma unroll
            for (int j4 = 0; j4 < 4; j4++) {
                float4 q4 = *(const float4*)(qrow + j4 * 4);
                acc[i] = fmaf(q4.x, sinr[j4 * 4 + 0], acc[i]);
                acc[i] = fmaf(q4.y, sinr[j4 * 4 + 1], acc[i]);
                acc[i] = fmaf(q4.z, sinr[j4 * 4 + 2], acc[i]);
                acc[i] = fmaf(q4.w, sinr[j4 * 4 + 3], acc[i]);
            }
        }
    }

#pragma unroll
    for (int i = 0; i < TPT; i++) {
        const int ti = tg + i * 4;
        float val = acc[i] * g_gate[cbase + (size_t)ti * Dv + v];
        g_o_h[cbase + (size_t)ti * Dv + v] = __float2half_rn(val);
    }
}

// ---------------- launch ----------------
#define GEMM_SMEM 65536

extern "C" void kernel_launch(void* const* d_in, const int* in_sizes, int n_in,
                              void* d_out, int out_size)
{
    const float* x      = (const float*)d_in[0];
    const float* maa_x  = (const float*)d_in[1];
    const float* maa_r  = (const float*)d_in[2];
    const float* maa_k  = (const float*)d_in[3];
    const float* maa_v  = (const float*)d_in[4];
    const float* maa_w  = (const float*)d_in[5];
    const float* maa_g  = (const float*)d_in[6];
    const float* w1     = (const float*)d_in[7];
    const float* w2     = (const float*)d_in[8];
    const float* tdecay = (const float*)d_in[9];
    const float* dw1    = (const float*)d_in[10];
    const float* dw2    = (const float*)d_in[11];
    const float* Wq     = (const float*)d_in[12];
    const float* Wk     = (const float*)d_in[13];
    const float* Wv     = (const float*)d_in[14];
    const float* Wo     = (const float*)d_in[15];
    const float* Wg     = (const float*)d_in[16];
    const float* bg     = (const float*)d_in[17];
    float* out = (float*)d_out;

    __half* p_w16;
    cudaGetSymbolAddress((void**)&p_w16, g_w16);

    cudaFuncSetAttribute(mixpre_kernel, cudaFuncAttributeMaxDynamicSharedMemorySize, GEMM_SMEM);
    cudaFuncSetAttribute(proj_kernel,   cudaFuncAttributeMaxDynamicSharedMemorySize, GEMM_SMEM);
    cudaFuncSetAttribute(glog_kernel,   cudaFuncAttributeMaxDynamicSharedMemorySize, GEMM_SMEM);
    cudaFuncSetAttribute(wo_kernel,     cudaFuncAttributeMaxDynamicSharedMemorySize, GEMM_SMEM);
    cudaFuncSetAttribute(mix5_kernel,   cudaFuncAttributeMaxDynamicSharedMemorySize, MF_SMEM);
    cudaFuncSetAttribute(scan3_kernel,  cudaFuncAttributeMaxDynamicSharedMemorySize, S3_SMEM);

    dim3 blk(256);

    // 1
    shift_kernel<<<NELEM / 256, blk>>>(x, maa_x);
    // 2
    wprep_all<<<dim3(32, 32, 8), dim3(32, 32)>>>(Wq, Wk, Wv, Wg, Wo, dw1, dw2, w1, p_w16);
    // 3
    mixpre_kernel<<<dim3(2, 32), blk, GEMM_SMEM>>>(p_w16);
    // 4  <-- profiled launch
    mix5_kernel<<<dim3(8, 128), blk, MF_SMEM>>>(x, w2, maa_r, maa_k, maa_v, maa_w, maa_g);
    // 5
    proj_kernel<<<dim3(8, 32, 5), blk, GEMM_SMEM>>>(p_w16, bg);
    // 6
    glog_kernel<<<dim3(8, 32), blk, GEMM_SMEM>>>(p_w16, tdecay);
    // 7-9: chunked scan
    scan1_kernel<<<dim3(NCk, 32), blk>>>();
    scan2_kernel<<<32, blk>>>();
    scan3_kernel<<<dim3(NCk, 32), blk, S3_SMEM>>>();
    // 10
    wo_kernel<<<dim3(8, 32), blk, GEMM_SMEM>>>(p_w16, out);
}

// round 17
// speedup vs baseline: 1.0251x; 1.0251x over previous
#include <cuda_runtime.h>
#include <cuda_fp16.h>
#include <math.h>
#include <stdint.h>

#define Bv 2
#define Tv 2048
#define Dv 1024
#define Hv 16
#define HDv 64
#define Mv (Bv*Tv)
#define NELEM (Mv*Dv)
#define NCk 32      // chunks per sequence
#define CLk 64      // chunk length

// ---------------- helpers ----------------
__device__ __forceinline__ uint32_t smem_u32(const void* p) {
    uint32_t a;
    asm("{ .reg .u64 t; cvta.to.shared.u64 t, %1; cvt.u32.u64 %0, t; }" : "=r"(a) : "l"(p));
    return a;
}
#define SWZ(off) ((off) ^ (((off) >> 3) & 0x70))

__device__ __forceinline__ void ldsm_x4(uint32_t* r, uint32_t addr) {
    asm volatile("ldmatrix.sync.aligned.m8n8.x4.shared.b16 {%0,%1,%2,%3}, [%4];"
        : "=r"(r[0]), "=r"(r[1]), "=r"(r[2]), "=r"(r[3]) : "r"(addr));
}
__device__ __forceinline__ void hmma(float* c, const uint32_t* a, const uint32_t* b) {
    asm volatile(
        "mma.sync.aligned.m16n8k16.row.col.f32.f16.f16.f32 "
        "{%0,%1,%2,%3}, {%4,%5,%6,%7}, {%8,%9}, {%0,%1,%2,%3};"
        : "+f"(c[0]), "+f"(c[1]), "+f"(c[2]), "+f"(c[3])
        : "r"(a[0]), "r"(a[1]), "r"(a[2]), "r"(a[3]), "r"(b[0]), "r"(b[1]));
}
__device__ __forceinline__ void cp16(uint32_t dst, const void* src, int srcsize) {
    asm volatile("cp.async.cg.shared.global [%0], [%1], 16, %2;"
        :: "r"(dst), "l"(src), "r"(srcsize) : "memory");
}
#define CP_COMMIT() asm volatile("cp.async.commit_group;" ::: "memory")
#define CP_WAIT(N)  asm volatile("cp.async.wait_group %0;" :: "n"(N) : "memory")

__device__ __forceinline__ uint32_t h2u(__half a, __half b) {
    __half2 p = __halves2half2(a, b);
    return *reinterpret_cast<uint32_t*>(&p);
}

// ---------------- scratch globals ----------------
__device__ __align__(16) float g_mixt[Mv*160];
__device__ __align__(16) float g_q[NELEM];
__device__ __align__(16) float g_k[NELEM];
__device__ __align__(16) float g_v[NELEM];
__device__ __align__(16) float g_gate[NELEM];
__device__ __align__(16) float g_e[NELEM];          // exp(glog), fp32

// chunked-scan scratch
__device__ __align__(16) float g_oloc[NELEM];
__device__ __align__(16) float g_qd[NELEM];
__device__ __align__(16) float g_slocal[32 * NCk * 4096];
__device__ __align__(16) float g_sin[32 * NCk * 4096];
__device__ __align__(16) float g_dprod[32 * NCk * 64];

// fp16 activations
__device__ __align__(16) __half g_xx_h[NELEM];
__device__ __align__(16) __half g_xr_h[NELEM];
__device__ __align__(16) __half g_xk_h[NELEM];
__device__ __align__(16) __half g_xv_h[NELEM];
__device__ __align__(16) __half g_xw_h[NELEM];
__device__ __align__(16) __half g_xg_h[NELEM];
__device__ __align__(16) __half g_dt_h[Mv*64];
__device__ __align__(16) __half g_o_h[NELEM];

// weight pool (transposed, fp16): [N][K]
#define OFF_WQ  0
#define OFF_WK  1048576
#define OFF_WV  2097152
#define OFF_WG  3145728
#define OFF_WO  4194304
#define OFF_DW1 5242880
#define OFF_DW2 (5242880 + 65536)
#define OFF_W1  (5242880 + 131072)
#define WPOOL_SZ (5242880 + 131072 + 163840)
__device__ __align__(16) __half g_w16[WPOOL_SZ];

// ---------------- elementwise ----------------
// xx = x + (xprev - x)*maa_x -> fp16  (xprev = 0 at t=0)
__global__ __launch_bounds__(256) void shift_kernel(const float* __restrict__ x,
                                                    const float* __restrict__ maa_x) {
    int i = blockIdx.x * 256 + threadIdx.x;
    float xv = x[i];
    int d  = i & (Dv - 1);
    int tt = (i >> 10) & (Tv - 1);
    float xp = (tt > 0) ? x[i - Dv] : 0.f;
    g_xx_h[i] = __float2half_rn(fmaf(xp - xv, maa_x[d], xv));
}

// all weights: W[K][N] -> fp16 [N][K] in pool
__global__ __launch_bounds__(1024)
void wprep_all(const float* __restrict__ Wq, const float* __restrict__ Wk,
               const float* __restrict__ Wv, const float* __restrict__ Wg,
               const float* __restrict__ Wo, const float* __restrict__ dw1,
               const float* __restrict__ dw2, const float* __restrict__ w1,
               __half* __restrict__ pool)
{
    __shared__ float tile[32][33];
    const float* W; int K, N; int off;
    switch (blockIdx.z) {
        case 0: W = Wq;  K = 1024; N = 1024; off = OFF_WQ;  break;
        case 1: W = Wk;  K = 1024; N = 1024; off = OFF_WK;  break;
        case 2: W = Wv;  K = 1024; N = 1024; off = OFF_WV;  break;
        case 3: W = Wg;  K = 1024; N = 1024; off = OFF_WG;  break;
        case 4: W = Wo;  K = 1024; N = 1024; off = OFF_WO;  break;
        case 5: W = dw1; K = 1024; N = 64;   off = OFF_DW1; break;
        case 6: W = dw2; K = 64;   N = 1024; off = OFF_DW2; break;
        default:W = w1;  K = 1024; N = 160;  off = OFF_W1;  break;
    }
    int bx = blockIdx.x, by = blockIdx.y;
    if (bx * 32 >= N || by * 32 >= K) return;
    int tx = threadIdx.x, ty = threadIdx.y;
    tile[ty][tx] = W[(size_t)(by * 32 + ty) * N + bx * 32 + tx];
    __syncthreads();
    int n2 = bx * 32 + ty, k2 = by * 32 + tx;
    if (n2 < N)
        pool[off + (size_t)n2 * K + k2] = __float2half_rn(tile[tx][ty]);
}

// ---------------- GEMM core: single-pass fp16, cp.async 2-stage ----------------
// epi: 0 = acc*scale ; 1 = tanh ; 2 = exp(-exp(bias[n]+acc)) ; 3 = silu(acc+bias[n])
__device__ __forceinline__ void gemm_core(
    const __half* __restrict__ Ah, const __half* __restrict__ Bm,
    const float* __restrict__ bias,
    float* __restrict__ Cf, __half* __restrict__ Chi,
    int ldC, int Ntot, int K, float scale, int epi, int osplit,
    int m0, int n0, uint32_t sb0)
{
    constexpr uint32_t STAGE = 32768;
    constexpr uint32_t A_OF = 0, B_OF = 16384;
    const int t = threadIdx.x, wid = t >> 5, lane = t & 31;
    const int wm = (wid & 1) * 64, wn = (wid >> 1) * 32;
    const int ldrow = t >> 3;
    const int kseg = (t & 7) * 8;
    const uint32_t dsw = SWZ((uint32_t)(ldrow * 128 + (t & 7) * 16));
    const int nch = K >> 6;

    auto issue = [&](int c) {
        const int k0 = c << 6;
        const uint32_t sb = sb0 + (uint32_t)(c & 1) * STAGE;
#pragma unroll
        for (int it = 0; it < 4; it++) {
            int row = it * 32 + ldrow;
            size_t ga = (size_t)(m0 + row) * K + k0 + kseg;
            cp16(sb + A_OF + it * 4096 + dsw, Ah + ga, 16);
            int nr = n0 + row;
            int ss = (nr < Ntot) ? 16 : 0;
            size_t gb = (size_t)(nr < Ntot ? nr : 0) * K + k0 + kseg;
            cp16(sb + B_OF + it * 4096 + dsw, Bm + gb, ss);
        }
        CP_COMMIT();
    };

    issue(0);

    float acc[4][4][4];
#pragma unroll
    for (int a = 0; a < 4; a++)
#pragma unroll
        for (int b = 0; b < 4; b++)
#pragma unroll
            for (int cc = 0; cc < 4; cc++) acc[a][b][cc] = 0.f;

    const int rowA_l = (lane & 7) + ((lane >> 3) & 1) * 8;
    const int koffA  = ((lane >> 4) & 1) * 16;
    const uint32_t xorA = (uint32_t)((rowA_l & 7) << 4);
    const int rowB_l = (lane & 7) + ((lane >> 4) & 1) * 8;
    const int koffB  = ((lane >> 3) & 1) * 16;
    const uint32_t xorB = (uint32_t)((rowB_l & 7) << 4);

    for (int c = 0; c < nch; c++) {
        if (c + 1 < nch) { issue(c + 1); CP_WAIT(1); }
        else             { CP_WAIT(0); }
        __syncthreads();
        const uint32_t sb = sb0 + (uint32_t)(c & 1) * STAGE;
#pragma unroll
        for (int ks = 0; ks < 4; ks++) {
            const uint32_t kbA = (uint32_t)(ks * 32 + koffA) ^ xorA;
            const uint32_t kbB = (uint32_t)(ks * 32 + koffB) ^ xorB;
            uint32_t bf[4][2];
#pragma unroll
            for (int pt = 0; pt < 2; pt++) {
                uint32_t r[4];
                uint32_t baddr = (uint32_t)((wn + pt * 16 + rowB_l) * 128) + kbB;
                ldsm_x4(r, sb + B_OF + baddr);
                bf[2*pt][0] = r[0]; bf[2*pt][1] = r[1];
                bf[2*pt+1][0] = r[2]; bf[2*pt+1][1] = r[3];
            }
#pragma unroll
            for (int mi = 0; mi < 4; mi++) {
                uint32_t ah[4];
                uint32_t aaddr = (uint32_t)((wm + mi * 16 + rowA_l) * 128) + kbA;
                ldsm_x4(ah, sb + A_OF + aaddr);
#pragma unroll
                for (int ni = 0; ni < 4; ni++)
                    hmma(acc[mi][ni], ah, bf[ni]);
            }
        }
        __syncthreads();
    }

    // epilogue
    const int rfrag = lane >> 2;
    const int cfrag = (lane & 3) * 2;
#pragma unroll
    for (int mi = 0; mi < 4; mi++) {
#pragma unroll
        for (int ni = 0; ni < 4; ni++) {
            int n = n0 + wn + ni * 8 + cfrag;
            if (n >= Ntot) continue;
            int r0 = m0 + wm + mi * 16 + rfrag;
            float b0 = 0.f, b1 = 0.f;
            if (epi == 2 || epi == 3) { b0 = bias[n]; b1 = bias[n + 1]; }
#pragma unroll
            for (int hh = 0; hh < 2; hh++) {
                float vx = acc[mi][ni][hh * 2], vy = acc[mi][ni][hh * 2 + 1];
                float ox, oy;
                if (epi == 0)      { ox = vx * scale; oy = vy * scale; }
                else if (epi == 1) { ox = tanhf(vx); oy = tanhf(vy); }
                else if (epi == 2) { ox = expf(-expf(b0 + vx)); oy = expf(-expf(b1 + vy)); }
                else {
                    float z0 = vx + b0, z1 = vy + b1;
                    ox = z0 / (1.f + expf(-z0)); oy = z1 / (1.f + expf(-z1));
                }
                size_t idx = (size_t)(r0 + hh * 8) * ldC + n;
                if (osplit) {
                    *(uint32_t*)(Chi + idx) = h2u(__float2half_rn(ox), __float2half_rn(oy));
                } else {
                    *(float2*)(Cf + idx) = make_float2(ox, oy);
                }
            }
        }
    }
}

// ---- GEMM wrappers ----
__global__ __launch_bounds__(256, 2)
void mixpre_kernel(const __half* __restrict__ wpool)
{
    extern __shared__ char smraw[];
    gemm_core(g_xx_h, wpool + OFF_W1, nullptr, g_mixt, nullptr,
              160, 160, 1024, 1.f, 1, 0, blockIdx.y * 128, blockIdx.x * 128, smem_u32(smraw));
}

__global__ __launch_bounds__(256, 2)
void proj_kernel(const __half* __restrict__ wpool, const float* __restrict__ bg)
{
    extern __shared__ char smraw[];
    int z = blockIdx.z;
    if (z == 4 && blockIdx.x > 0) return;
    const __half *Ah, *Bm;
    const float* bias = nullptr;
    float* Cf = nullptr; __half* Chi = nullptr;
    int Ntot = 1024, ldC = 1024, epi = 0, osplit = 0;
    float scale = 1.f;
    switch (z) {
        case 0: Ah = g_xr_h; Bm = wpool + OFF_WQ; Cf = g_q; scale = 0.125f; break;
        case 1: Ah = g_xk_h; Bm = wpool + OFF_WK; Cf = g_k; break;
        case 2: Ah = g_xv_h; Bm = wpool + OFF_WV; Cf = g_v; break;
        case 3: Ah = g_xg_h; Bm = wpool + OFF_WG; bias = bg; Cf = g_gate; epi = 3; break;
        default: Ah = g_xw_h; Bm = wpool + OFF_DW1;
                 Chi = g_dt_h; Ntot = 64; ldC = 64; epi = 1; osplit = 1; break;
    }
    gemm_core(Ah, Bm, bias, Cf, Chi, ldC, Ntot, 1024, scale, epi, osplit,
              blockIdx.y * 128, blockIdx.x * 128, smem_u32(smraw));
}

// e = exp(glog) = exp(-exp(tdecay + dt@dw2)), stored fp32
__global__ __launch_bounds__(256, 2)
void glog_kernel(const __half* __restrict__ wpool, const float* __restrict__ tdecay)
{
    extern __shared__ char smraw[];
    gemm_core(g_dt_h, wpool + OFF_DW2, tdecay, g_e, nullptr,
              1024, 1024, 64, 1.f, 2, 0, blockIdx.y * 128, blockIdx.x * 128, smem_u32(smraw));
}

__global__ __launch_bounds__(256, 2)
void wo_kernel(const __half* __restrict__ wpool, float* __restrict__ out)
{
    extern __shared__ char smraw[];
    gemm_core(g_o_h, wpool + OFF_WO, nullptr, out, nullptr,
              1024, 1024, 1024, 1.f, 0, 0, blockIdx.y * 128, blockIdx.x * 128, smem_u32(smraw));
}

// ---------------- 5-stream mix (dx fused, fp16 out) ----------------
#define MF_SMEM 55296
__global__ __launch_bounds__(256)
void mix5_kernel(const float* __restrict__ x, const float* __restrict__ w2,
                 const float* __restrict__ mr, const float* __restrict__ mk,
                 const float* __restrict__ mv_, const float* __restrict__ mw,
                 const float* __restrict__ mg)
{
    extern __shared__ float sm[];
    float* smixt = sm;            // [32][160]
    float* sw2   = sm + 5120;     // [32][128]
    float* sxt   = sm + 9216;     // [33][128]

    const int t = threadIdx.x;
    const int c0 = blockIdx.x * 128;
    const int m0 = blockIdx.y * 32;
    const int tx = t & 31, ty = t >> 5;

    for (int i = t; i < 1280; i += 256) {
        int row = i / 40, c4 = i % 40;
        *(float4*)&smixt[row * 160 + c4 * 4] =
            *(const float4*)(g_mixt + (size_t)(m0 + row) * 160 + c4 * 4);
    }
    // x rows m0-1 .. m0+31; sequence-start boundary row = zeros
    for (int i = t; i < 33 * 32; i += 256) {
        int row = i >> 5, c4 = i & 31;
        float4 val;
        if (row == 0 && (m0 & (Tv - 1)) == 0) {
            val = make_float4(0.f, 0.f, 0.f, 0.f);
        } else {
            int grow = m0 + row - 1;
            val = *(const float4*)(x + (size_t)grow * 1024 + c0 + c4 * 4);
        }
        *(float4*)&sxt[row * 128 + c4 * 4] = val;
    }

    const float* maas[5] = {mr, mk, mv_, mw, mg};
    __half* oh[5] = {g_xr_h, g_xk_h, g_xv_h, g_xw_h, g_xg_h};

#pragma unroll 1
    for (int s = 0; s < 5; s++) {
        __syncthreads();
        for (int i = t; i < 1024; i += 256) {
            int row = i >> 5, c4 = i & 31;
            *(float4*)&sw2[row * 128 + c4 * 4] =
                *(const float4*)(w2 + ((size_t)s * 32 + row) * 1024 + c0 + c4 * 4);
        }
        __syncthreads();

        float acc[4][4];
#pragma unroll
        for (int i = 0; i < 4; i++)
#pragma unroll
            for (int j = 0; j < 4; j++) acc[i][j] = 0.f;
#pragma unroll
        for (int k4 = 0; k4 < 8; k4++) {
            float4 a4[4];
#pragma unroll
            for (int i = 0; i < 4; i++)
                a4[i] = *(const float4*)&smixt[(ty * 4 + i) * 160 + s * 32 + k4 * 4];
#pragma unroll
            for (int kk = 0; kk < 4; kk++) {
                float4 w4 = *(const float4*)&sw2[(k4 * 4 + kk) * 128 + tx * 4];
#pragma unroll
                for (int i = 0; i < 4; i++) {
                    float a = (kk == 0) ? a4[i].x : (kk == 1) ? a4[i].y
                             : (kk == 2) ? a4[i].z : a4[i].w;
                    acc[i][0] = fmaf(a, w4.x, acc[i][0]);
                    acc[i][1] = fmaf(a, w4.y, acc[i][1]);
                    acc[i][2] = fmaf(a, w4.z, acc[i][2]);
                    acc[i][3] = fmaf(a, w4.w, acc[i][3]);
                }
            }
        }

        float4 ma4 = *(const float4*)(maas[s] + c0 + tx * 4);
        __half* ohp = oh[s];
#pragma unroll
        for (int i = 0; i < 4; i++) {
            int row = ty * 4 + i;
            float4 xv4 = *(const float4*)&sxt[(row + 1) * 128 + tx * 4];
            float4 xp4 = *(const float4*)&sxt[row * 128 + tx * 4];
            float o0 = fmaf(xp4.x - xv4.x, ma4.x + acc[i][0], xv4.x);
            float o1 = fmaf(xp4.y - xv4.y, ma4.y + acc[i][1], xv4.y);
            float o2 = fmaf(xp4.z - xv4.z, ma4.z + acc[i][2], xv4.z);
            float o3 = fmaf(xp4.w - xv4.w, ma4.w + acc[i][3], xv4.w);
            size_t gi = (size_t)(m0 + row) * 1024 + c0 + tx * 4;
            *(uint2*)(ohp + gi) = make_uint2(
                h2u(__float2half_rn(o0), __float2half_rn(o1)),
                h2u(__float2half_rn(o2), __float2half_rn(o3)));
        }
    }
}

// ---------------- chunked scan ----------------
// roles: kg0 -> q, kg1 -> k*(1-e), kg2 -> e, kg3 -> v   (all fp32, e precomputed)
#define S1_LOAD(T_, R) do { \
    size_t off = cbase + (size_t)(T_) * Dv; \
    if (kg == 0)      R = g_q[off + lidx]; \
    else if (kg == 1) { size_t i = off + lidx; R = g_k[i] * (1.f - g_e[i]); } \
    else if (kg == 2) R = g_e[off + lidx]; \
    else              R = g_v[off + lidx]; \
} while (0)

__global__ __launch_bounds__(256)
void scan1_kernel() {
    const int bh = blockIdx.y;
    const int b = bh >> 4, h = bh & 15;
    const int c = blockIdx.x;
    const int tid = threadIdx.x;
    const int vcol = tid & 63;
    const int kg = tid >> 6;
    const int k0 = kg * 16;
    const int lidx = tid & 63;

    __shared__ __align__(16) float sq[64];
    __shared__ __align__(16) float sk[64];
    __shared__ __align__(16) float se[64];
    __shared__ __align__(16) float sv[64];
    __shared__ float spart[4][64];

    float S[16];
#pragma unroll
    for (int j = 0; j < 16; j++) S[j] = 0.f;
    float cum = 1.f;

    const size_t base0 = (size_t)b * Tv * Dv + h * HDv;
    const size_t cbase = base0 + (size_t)(c * CLk) * Dv;

    float r0, r1;
    S1_LOAD(0, r0);
    S1_LOAD(1, r1);

    for (int t = 0; t < CLk; t += 2) {
        if (kg == 0)      sq[lidx] = r0;
        else if (kg == 1) sk[lidx] = r0;
        else if (kg == 2) { se[lidx] = r0; cum *= r0; }
        else              sv[lidx] = r0;
        __syncthreads();
        if (t + 2 < CLk) S1_LOAD(t + 2, r0);
        if (kg == 2) g_qd[cbase + (size_t)t * Dv + lidx] = cum * sq[lidx];
        {
            const float vv = sv[vcol];
            float p0 = 0.f, p1 = 0.f;
#pragma unroll
            for (int jj = 0; jj < 4; jj++) {
                float4 e4 = *(const float4*)&se[k0 + jj * 4];
                float4 k4 = *(const float4*)&sk[k0 + jj * 4];
                float4 q4 = *(const float4*)&sq[k0 + jj * 4];
                S[jj*4+0] = fmaf(S[jj*4+0], e4.x, k4.x * vv); p0 = fmaf(q4.x, S[jj*4+0], p0);
                S[jj*4+1] = fmaf(S[jj*4+1], e4.y, k4.y * vv); p1 = fmaf(q4.y, S[jj*4+1], p1);
                S[jj*4+2] = fmaf(S[jj*4+2], e4.z, k4.z * vv); p0 = fmaf(q4.z, S[jj*4+2], p0);
                S[jj*4+3] = fmaf(S[jj*4+3], e4.w, k4.w * vv); p1 = fmaf(q4.w, S[jj*4+3], p1);
            }
            spart[kg][vcol] = p0 + p1;
        }
        __syncthreads();
        if (kg == 0)
            g_oloc[cbase + (size_t)t * Dv + vcol] =
                spart[0][vcol] + spart[1][vcol] + spart[2][vcol] + spart[3][vcol];

        if (kg == 0)      sq[lidx] = r1;
        else if (kg == 1) sk[lidx] = r1;
        else if (kg == 2) { se[lidx] = r1; cum *= r1; }
        else              sv[lidx] = r1;
        __syncthreads();
        if (t + 3 < CLk) S1_LOAD(t + 3, r1);
        if (kg == 2) g_qd[cbase + (size_t)(t + 1) * Dv + lidx] = cum * sq[lidx];
        {
            const float vv = sv[vcol];
            float p0 = 0.f, p1 = 0.f;
#pragma unroll
            for (int jj = 0; jj < 4; jj++) {
                float4 e4 = *(const float4*)&se[k0 + jj * 4];
                float4 k4 = *(const float4*)&sk[k0 + jj * 4];
                float4 q4 = *(const float4*)&sq[k0 + jj * 4];
                S[jj*4+0] = fmaf(S[jj*4+0], e4.x, k4.x * vv); p0 = fmaf(q4.x, S[jj*4+0], p0);
                S[jj*4+1] = fmaf(S[jj*4+1], e4.y, k4.y * vv); p1 = fmaf(q4.y, S[jj*4+1], p1);
                S[jj*4+2] = fmaf(S[jj*4+2], e4.z, k4.z * vv); p0 = fmaf(q4.z, S[jj*4+2], p0);
                S[jj*4+3] = fmaf(S[jj*4+3], e4.w, k4.w * vv); p1 = fmaf(q4.w, S[jj*4+3], p1);
            }
            spart[kg][vcol] = p0 + p1;
        }
        __syncthreads();
        if (kg == 0)
            g_oloc[cbase + (size_t)(t + 1) * Dv + vcol] =
                spart[0][vcol] + spart[1][vcol] + spart[2][vcol] + spart[3][vcol];
    }

    size_t sbase = (size_t)(bh * NCk + c) * 4096;
#pragma unroll
    for (int j = 0; j < 16; j++)
        g_slocal[sbase + (size_t)(k0 + j) * 64 + vcol] = S[j];
    if (kg == 2)
        g_dprod[(bh * NCk + c) * 64 + lidx] = cum;
}

// scan2: diagonal combine across chunks, one (bh, cell) chain per thread.
// grid (16, 32) = 512 blocks for full-chip occupancy.
__global__ __launch_bounds__(256)
void scan2_kernel() {
    const int bh = blockIdx.y;
    const int cell = blockIdx.x * 256 + threadIdx.x;   // 0..4095
    const int drow = cell >> 6;
    float s = 0.f;
    for (int c = 0; c < NCk; c++) {
        size_t base = (size_t)(bh * NCk + c) * 4096;
        g_sin[base + cell] = s;
        float dp = g_dprod[(bh * NCk + c) * 64 + drow];
        s = fmaf(dp, s, g_slocal[base + cell]);
    }
}

// scan3: o_t = (o_loc_t + Qd_t . S_in) * gate -> fp16 output
#define S3_SMEM 32768
__global__ __launch_bounds__(256)
void scan3_kernel() {
    extern __shared__ float s3[];
    float* ssin = s3;              // 4096
    float* sqd  = s3 + 4096;       // 4096

    const int bh = blockIdx.y;
    const int b = bh >> 4, h = bh & 15;
    const int c = blockIdx.x;
    const int tid = threadIdx.x;
    const size_t base0 = (size_t)b * Tv * Dv + h * HDv;
    const size_t cbase = base0 + (size_t)(c * CLk) * Dv;

    {
        const float* sinp = g_sin + (size_t)(bh * NCk + c) * 4096;
        for (int i = tid; i < 1024; i += 256)
            *(float4*)&ssin[i * 4] = *(const float4*)(sinp + i * 4);
        for (int i = tid; i < CLk * 16; i += 256) {
            int row = i >> 4, cg = i & 15;
            *(float4*)&sqd[row * 64 + cg * 4] =
                *(const float4*)(g_qd + cbase + (size_t)row * Dv + cg * 4);
        }
    }
    __syncthreads();

    const int tg = tid >> 6;
    const int v = tid & 63;
    constexpr int TPT = CLk / 4;

    float acc[TPT];
#pragma unroll
    for (int i = 0; i < TPT; i++)
        acc[i] = g_oloc[cbase + (size_t)(tg + i * 4) * Dv + v];

#pragma unroll 1
    for (int kb = 0; kb < 64; kb += 16) {
        float sinr[16];
#pragma unroll
        for (int j = 0; j < 16; j++) sinr[j] = ssin[(kb + j) * 64 + v];
#pragma unroll
        for (int i = 0; i < TPT; i++) {
            const int ti = tg + i * 4;
            const float* qrow = &sqd[ti * 64 + kb];
#pragma unroll
            for (int j4 = 0; j4 < 4; j4++) {
                float4 q4 = *(const float4*)(qrow + j4 * 4);
                acc[i] = fmaf(q4.x, sinr[j4 * 4 + 0], acc[i]);
                acc[i] = fmaf(q4.y, sinr[j4 * 4 + 1], acc[i]);
                acc[i] = fmaf(q4.z, sinr[j4 * 4 + 2], acc[i]);
                acc[i] = fmaf(q4.w, sinr[j4 * 4 + 3], acc[i]);
            }
        }
    }

#pragma unroll
    for (int i = 0; i < TPT; i++) {
        const int ti = tg + i * 4;
        float val = acc[i] * g_gate[cbase + (size_t)ti * Dv + v];
        g_o_h[cbase + (size_t)ti * Dv + v] = __float2half_rn(val);
    }
}

// ---------------- launch ----------------
#define GEMM_SMEM 65536

extern "C" void kernel_launch(void* const* d_in, const int* in_sizes, int n_in,
                              void* d_out, int out_size)
{
    const float* x      = (const float*)d_in[0];
    const float* maa_x  = (const float*)d_in[1];
    const float* maa_r  = (const float*)d_in[2];
    const float* maa_k  = (const float*)d_in[3];
    const float* maa_v  = (const float*)d_in[4];
    const float* maa_w  = (const float*)d_in[5];
    const float* maa_g  = (const float*)d_in[6];
    const float* w1     = (const float*)d_in[7];
    const float* w2     = (const float*)d_in[8];
    const float* tdecay = (const float*)d_in[9];
    const float* dw1    = (const float*)d_in[10];
    const float* dw2    = (const float*)d_in[11];
    const float* Wq     = (const float*)d_in[12];
    const float* Wk     = (const float*)d_in[13];
    const float* Wv     = (const float*)d_in[14];
    const float* Wo     = (const float*)d_in[15];
    const float* Wg     = (const float*)d_in[16];
    const float* bg     = (const float*)d_in[17];
    float* out = (float*)d_out;

    __half* p_w16;
    cudaGetSymbolAddress((void**)&p_w16, g_w16);

    cudaFuncSetAttribute(mixpre_kernel, cudaFuncAttributeMaxDynamicSharedMemorySize, GEMM_SMEM);
    cudaFuncSetAttribute(proj_kernel,   cudaFuncAttributeMaxDynamicSharedMemorySize, GEMM_SMEM);
    cudaFuncSetAttribute(glog_kernel,   cudaFuncAttributeMaxDynamicSharedMemorySize, GEMM_SMEM);
    cudaFuncSetAttribute(wo_kernel,     cudaFuncAttributeMaxDynamicSharedMemorySize, GEMM_SMEM);
    cudaFuncSetAttribute(mix5_kernel,   cudaFuncAttributeMaxDynamicSharedMemorySize, MF_SMEM);
    cudaFuncSetAttribute(scan3_kernel,  cudaFuncAttributeMaxDynamicSharedMemorySize, S3_SMEM);

    dim3 blk(256);

    // 1
    shift_kernel<<<NELEM / 256, blk>>>(x, maa_x);
    // 2
    wprep_all<<<dim3(32, 32, 8), dim3(32, 32)>>>(Wq, Wk, Wv, Wg, Wo, dw1, dw2, w1, p_w16);
    // 3
    mixpre_kernel<<<dim3(2, 32), blk, GEMM_SMEM>>>(p_w16);
    // 4  <-- profiled launch
    mix5_kernel<<<dim3(8, 128), blk, MF_SMEM>>>(x, w2, maa_r, maa_k, maa_v, maa_w, maa_g);
    // 5
    proj_kernel<<<dim3(8, 32, 5), blk, GEMM_SMEM>>>(p_w16, bg);
    // 6
    glog_kernel<<<dim3(8, 32), blk, GEMM_SMEM>>>(p_w16, tdecay);
    // 7-9: chunked scan
    scan1_kernel<<<dim3(NCk, 32), blk>>>();
    scan2_kernel<<<dim3(16, 32), blk>>>();
    scan3_kernel<<<dim3(NCk, 32), blk, S3_SMEM>>>();
    // 10
    wo_kernel<<<dim3(8, 32), blk, GEMM_SMEM>>>(p_w16, out);
}